// round 4
// baseline (speedup 1.0000x reference)
#include <cuda_runtime.h>
#include <cuda_bf16.h>

typedef unsigned long long u64;

#define T_N 4096
#define F_N 16
#define H_N 64

// ---- shared layout (float word offsets) ----
#define SWI   0        // input-side Wi1 weights: 3 dots * 128 (j,kc) * 12 pad = 4608
#define H1B   4608     // h1: 2 slots * 144  (per slot: [b][kc-half*36])
#define H2B   4896     // h2: 2 * 144
#define O1B   5184     // o1 ring: 4 * 144
#define XBUF  5760     // x ring: 4 slots * 2 b * 24 pad = 192
#define XI2B  5952     // xi2: 2 slots * 2 b * 192 = 768
#define XPB   6720     // xp: 2 slots * 2 b * 64 = 256
#define SCB   6976     // score partials: 2 slots * 2 b * 4 warps = 16
#define SATT  6992     // attended: 2*64 = 128
#define SM1   7120     // mlp h1: 2*128
#define SM2   7376     // mlp h2: 2*64
#define SM3   7504     // mlp h3: 2*32
#define STOT  7568

// packed f32x2 fma: d.lo += a.lo*b.lo ; d.hi += a.hi*b.hi
__device__ __forceinline__ void ffma2(u64 &d, u64 a, u64 b) {
    asm("fma.rn.f32x2 %0, %1, %2, %0;" : "+l"(d) : "l"(a), "l"(b));
}
__device__ __forceinline__ u64 pack2(float lo, float hi) {
    u64 r; asm("mov.b64 %0, {%1, %2};" : "=l"(r) : "f"(lo), "f"(hi)); return r;
}
// horizontal sum of the f32x2 acc + combine the two k-halves (lane ^ 1)
__device__ __forceinline__ float redu(u64 a) {
    float lo, hi;
    asm("mov.b64 {%0, %1}, %2;" : "=f"(lo), "=f"(hi) : "l"(a));
    float v = lo + hi;
    return v + __shfl_xor_sync(0xffffffffu, v, 1);
}
__device__ __forceinline__ float sigf(float v)     { return __fdividef(1.f, 1.f + __expf(-v)); }
__device__ __forceinline__ float tanhfast(float v) { return 1.f - __fdividef(2.f, __expf(2.f * v) + 1.f); }

// 3 matrices x 2 batches, 32-k half per thread, weights in registers.
__device__ __forceinline__ void dot6(const u64 (&wa)[16], const u64 (&wb)[16], const u64 (&wc)[16],
                                     const float* v0, const float* v1,
                                     u64 &a0, u64 &a1, u64 &a2, u64 &b0, u64 &b1, u64 &b2)
{
    const ulonglong2* h0 = reinterpret_cast<const ulonglong2*>(v0);
    const ulonglong2* h1 = reinterpret_cast<const ulonglong2*>(v1);
#pragma unroll
    for (int m = 0; m < 8; ++m) {
        ulonglong2 x0 = h0[m], x1 = h1[m];
        ffma2(a0, wa[2*m], x0.x); ffma2(a0, wa[2*m+1], x0.y);
        ffma2(a1, wb[2*m], x0.x); ffma2(a1, wb[2*m+1], x0.y);
        ffma2(a2, wc[2*m], x0.x); ffma2(a2, wc[2*m+1], x0.y);
        ffma2(b0, wa[2*m], x1.x); ffma2(b0, wa[2*m+1], x1.y);
        ffma2(b1, wb[2*m], x1.x); ffma2(b1, wb[2*m+1], x1.y);
        ffma2(b2, wc[2*m], x1.x); ffma2(b2, wc[2*m+1], x1.y);
    }
}

__global__ __launch_bounds__(384, 1)
void solar_fused(const float* __restrict__ x,
                 const float* __restrict__ Wi1,  const float* __restrict__ bi1,
                 const float* __restrict__ Whr1, const float* __restrict__ Whz1,
                 const float* __restrict__ Whn1, const float* __restrict__ bhn1,
                 const float* __restrict__ Wi2,  const float* __restrict__ bi2,
                 const float* __restrict__ Whr2, const float* __restrict__ Whz2,
                 const float* __restrict__ Whn2, const float* __restrict__ bhn2,
                 const float* __restrict__ Wp,   const float* __restrict__ bp,
                 const float* __restrict__ Wa,   const float* __restrict__ ba,
                 const float* __restrict__ W1,   const float* __restrict__ b1,
                 const float* __restrict__ W2,   const float* __restrict__ b2,
                 const float* __restrict__ W3,   const float* __restrict__ b3,
                 const float* __restrict__ W4,   const float* __restrict__ b4,
                 float* __restrict__ out)
{
    __shared__ __align__(16) float sm[STOT];

    const int tid  = threadIdx.x;
    const int grp  = tid >> 7;      // 0: L1-GRU, 1: Wi2+xproj, 2: L2-GRU+attn
    const int g    = tid & 127;
    const int j    = g >> 1;        // hidden column 0..63
    const int kc   = g & 1;         // k-half
    const int lane = tid & 31;
    const int wgrp = g >> 5;        // warp index within group 0..3
    const int widx = kc * 72 + (j >> 5) * 36 + (j & 31);  // scalar write/read slot in padded vec

    // ---------- register-resident weights ----------
    u64 wA[16], wB[16], wC[16], wD[4];
    float cb0 = 0.f, cb1 = 0.f, cb2 = 0.f, cb3 = 0.f;
    if (grp == 0) {
#pragma unroll
        for (int m = 0; m < 16; ++m) {
            int k = kc * 32 + 2 * m;
            wA[m] = pack2(Whr1[k*64 + j], Whr1[(k+1)*64 + j]);
            wB[m] = pack2(Whz1[k*64 + j], Whz1[(k+1)*64 + j]);
            wC[m] = pack2(Whn1[k*64 + j], Whn1[(k+1)*64 + j]);
        }
        cb0 = bi1[j]; cb1 = bi1[64 + j]; cb2 = bi1[128 + j]; cb3 = bhn1[j];
    } else if (grp == 1) {
#pragma unroll
        for (int m = 0; m < 16; ++m) {
            int k = kc * 32 + 2 * m;
            wA[m] = pack2(Wi2[k*192 + j],       Wi2[(k+1)*192 + j]);
            wB[m] = pack2(Wi2[k*192 + 64 + j],  Wi2[(k+1)*192 + 64 + j]);
            wC[m] = pack2(Wi2[k*192 + 128 + j], Wi2[(k+1)*192 + 128 + j]);
        }
#pragma unroll
        for (int m = 0; m < 4; ++m) {
            int f = kc * 8 + 2 * m;
            wD[m] = pack2(Wp[f*64 + j], Wp[(f+1)*64 + j]);
        }
        cb0 = bi2[j]; cb1 = bi2[64 + j]; cb2 = bi2[128 + j]; cb3 = bp[j];
    } else {
#pragma unroll
        for (int m = 0; m < 16; ++m) {
            int k = kc * 32 + 2 * m;
            wA[m] = pack2(Whr2[k*64 + j], Whr2[(k+1)*64 + j]);
            wB[m] = pack2(Whz2[k*64 + j], Whz2[(k+1)*64 + j]);
            wC[m] = pack2(Whn2[k*64 + j], Whn2[(k+1)*64 + j]);
        }
        cb0 = bhn2[j]; cb1 = Wa[j]; cb2 = ba[0];
    }

    // ---------- shared setup: input-side weights + zero state ----------
    for (int idx = tid; idx < 3 * 64 * 16; idx += 384) {
        int dot = idx >> 10;
        int rem = idx & 1023;
        int jj  = rem >> 4;
        int f   = rem & 15;
        int kh  = f >> 3, fl = f & 7;
        sm[SWI + (dot * 128 + jj * 2 + kh) * 12 + fl] = Wi1[f * 192 + dot * 64 + jj];
    }
    for (int idx = tid; idx < 576; idx += 384) sm[H1B + idx] = 0.f;  // h1 + h2, both slots

    // ---------- x prologue (loader: first 32 threads of group 2) ----------
    float rx = 0.f;
    size_t xbase = 0;
    if (grp == 2 && g < 32) {
        int b = g >> 4, f = g & 15;
        int bg = blockIdx.x * 2 + b;
        xbase = (size_t)bg * T_N * 16 + f;
        sm[XBUF + (0 * 2 + b) * 24 + f] = x[xbase];           // t=0 -> slot 0
        sm[XBUF + (1 * 2 + b) * 24 + f] = x[xbase + 16];      // t=1 -> slot 1
        rx = x[xbase + 32];                                    // t=2 held in reg
    }
    __syncthreads();

    // xp[t=0] precompute (group 1)
    if (grp == 1) {
        u64 p0 = 0, p1 = 0;
        const ulonglong2* x0 = reinterpret_cast<const ulonglong2*>(sm + XBUF + 0 * 24 + kc * 8);
        const ulonglong2* x1 = reinterpret_cast<const ulonglong2*>(sm + XBUF + 1 * 24 + kc * 8);
#pragma unroll
        for (int m = 0; m < 2; ++m) {
            ulonglong2 a = x0[m], b = x1[m];
            ffma2(p0, wD[2*m], a.x); ffma2(p0, wD[2*m+1], a.y);
            ffma2(p1, wD[2*m], b.x); ffma2(p1, wD[2*m+1], b.y);
        }
        float t0 = redu(p0), t1 = redu(p1);
        sm[XPB + 0 * 128 + kc * 64 + j] = (kc ? t1 : t0) + cb3;
    }
    __syncthreads();

    // ---------- pipelined recurrence ----------
    float am = -3.0e38f, as_ = 0.f, aacc = 0.f, po2 = 0.f;

    for (int i = 0; i <= T_N + 2; ++i) {
        if (grp == 0) {
            if (i < T_N) {
                int slot = i & 1;
                u64 r0 = 0, z0 = 0, nh0 = 0, r1 = 0, z1 = 0, nh1 = 0;
                dot6(wA, wB, wC,
                     sm + H1B + slot * 144 + 0 * 72 + kc * 36,
                     sm + H1B + slot * 144 + 1 * 72 + kc * 36,
                     r0, z0, nh0, r1, z1, nh1);
                // input-side contributions (weights from shared, tiny)
                u64 ni0 = 0, ni1 = 0;
                {
                    const ulonglong2* wiR = reinterpret_cast<const ulonglong2*>(sm + SWI + (0 * 128 + j * 2 + kc) * 12);
                    const ulonglong2* wiZ = reinterpret_cast<const ulonglong2*>(sm + SWI + (1 * 128 + j * 2 + kc) * 12);
                    const ulonglong2* wiN = reinterpret_cast<const ulonglong2*>(sm + SWI + (2 * 128 + j * 2 + kc) * 12);
                    const ulonglong2* x0p = reinterpret_cast<const ulonglong2*>(sm + XBUF + ((i & 3) * 2 + 0) * 24 + kc * 8);
                    const ulonglong2* x1p = reinterpret_cast<const ulonglong2*>(sm + XBUF + ((i & 3) * 2 + 1) * 24 + kc * 8);
#pragma unroll
                    for (int m = 0; m < 2; ++m) {
                        ulonglong2 xa = x0p[m], xb = x1p[m];
                        ulonglong2 wr = wiR[m], wz = wiZ[m], wn = wiN[m];
                        ffma2(r0,  wr.x, xa.x); ffma2(r0,  wr.y, xa.y);
                        ffma2(z0,  wz.x, xa.x); ffma2(z0,  wz.y, xa.y);
                        ffma2(ni0, wn.x, xa.x); ffma2(ni0, wn.y, xa.y);
                        ffma2(r1,  wr.x, xb.x); ffma2(r1,  wr.y, xb.y);
                        ffma2(z1,  wz.x, xb.x); ffma2(z1,  wz.y, xb.y);
                        ffma2(ni1, wn.x, xb.x); ffma2(ni1, wn.y, xb.y);
                    }
                }
                float tR0 = redu(r0),  tZ0 = redu(z0),  tNh0 = redu(nh0), tNi0 = redu(ni0);
                float tR1 = redu(r1),  tZ1 = redu(z1),  tNh1 = redu(nh1), tNi1 = redu(ni1);
                float tR  = kc ? tR1  : tR0,  tZ  = kc ? tZ1  : tZ0;
                float tNh = kc ? tNh1 : tNh0, tNi = kc ? tNi1 : tNi0;
                float hp = sm[H1B + slot * 144 + widx];
                float r  = sigf(tR + cb0);
                float z  = sigf(tZ + cb1);
                float n  = tanhfast(tNi + cb2 + r * (tNh + cb3));
                float hn = n + z * (hp - n);
                float xp = sm[XPB + slot * 128 + kc * 64 + j];
                sm[H1B + (slot ^ 1) * 144 + widx] = hn;
                sm[O1B + (i & 3) * 144 + widx]    = hn + 0.5f * xp;
            }
        } else if (grp == 1) {
            if (i >= 1 && i <= T_N) {   // xi2[t=i-1] = o1[t=i-1] @ Wi2 + bi2
                int os = (i - 1) & 3;
                u64 a0 = 0, a1 = 0, a2 = 0, b0 = 0, b1v = 0, b2v = 0;
                dot6(wA, wB, wC,
                     sm + O1B + os * 144 + 0 * 72 + kc * 36,
                     sm + O1B + os * 144 + 1 * 72 + kc * 36,
                     a0, a1, a2, b0, b1v, b2v);
                float t0 = redu(a0), t1 = redu(a1), t2 = redu(a2);
                float s0 = redu(b0), s1 = redu(b1v), s2 = redu(b2v);
                int base = XI2B + ((i - 1) & 1) * 384 + kc * 192;
                sm[base + j]        = (kc ? s0 : t0) + cb0;
                sm[base + 64 + j]   = (kc ? s1 : t1) + cb1;
                sm[base + 128 + j]  = (kc ? s2 : t2) + cb2;
            }
            if (i <= T_N - 2) {         // xp[t=i+1] = x[t=i+1] @ Wp + bp
                int xs = (i + 1) & 3;
                u64 p0 = 0, p1 = 0;
                const ulonglong2* x0p = reinterpret_cast<const ulonglong2*>(sm + XBUF + (xs * 2 + 0) * 24 + kc * 8);
                const ulonglong2* x1p = reinterpret_cast<const ulonglong2*>(sm + XBUF + (xs * 2 + 1) * 24 + kc * 8);
#pragma unroll
                for (int m = 0; m < 2; ++m) {
                    ulonglong2 a = x0p[m], b = x1p[m];
                    ffma2(p0, wD[2*m], a.x); ffma2(p0, wD[2*m+1], a.y);
                    ffma2(p1, wD[2*m], b.x); ffma2(p1, wD[2*m+1], b.y);
                }
                float t0 = redu(p0), t1 = redu(p1);
                sm[XPB + ((i + 1) & 1) * 128 + kc * 64 + j] = (kc ? t1 : t0) + cb3;
            }
        } else {
            if (i >= 3) {               // online softmax update for t = i-3
                const float* sp = sm + SCB + ((i - 1) & 1) * 8 + kc * 4;
                float sc   = sp[0] + sp[1] + sp[2] + sp[3] + cb2;
                float nm   = fmaxf(am, sc);
                float corr = __expf(am - nm);
                float p    = __expf(sc - nm);
                as_  = as_  * corr + p;
                aacc = aacc * corr + p * po2;
                am   = nm;
            }
            if (i >= 2 && i <= T_N + 1) {   // layer-2 GRU for t = i-2
                int hs = i & 1;
                u64 a0 = 0, a1 = 0, a2 = 0, b0 = 0, b1v = 0, b2v = 0;
                dot6(wA, wB, wC,
                     sm + H2B + hs * 144 + 0 * 72 + kc * 36,
                     sm + H2B + hs * 144 + 1 * 72 + kc * 36,
                     a0, a1, a2, b0, b1v, b2v);
                float t0 = redu(a0), t1 = redu(a1), t2 = redu(a2);
                float s0 = redu(b0), s1 = redu(b1v), s2 = redu(b2v);
                float tR  = kc ? s0 : t0;
                float tZ  = kc ? s1 : t1;
                float tNh = kc ? s2 : t2;
                int xb2 = XI2B + (i & 1) * 384 + kc * 192;
                float ir  = sm[xb2 + j], iz = sm[xb2 + 64 + j], inn = sm[xb2 + 128 + j];
                float hp  = sm[H2B + hs * 144 + widx];
                float r   = sigf(ir + tR);
                float z   = sigf(iz + tZ);
                float n   = tanhfast(inn + r * (tNh + cb0));
                float hn  = n + z * (hp - n);
                float o1r = sm[O1B + ((i - 2) & 3) * 144 + widx];
                float o2  = hn + 0.5f * o1r;
                po2 = o2;
                sm[H2B + (hs ^ 1) * 144 + widx] = hn;
                // score partial: sum over this warp's 16 j of same batch parity
                float part = o2 * cb1;
                part += __shfl_xor_sync(0xffffffffu, part, 2);
                part += __shfl_xor_sync(0xffffffffu, part, 4);
                part += __shfl_xor_sync(0xffffffffu, part, 8);
                part += __shfl_xor_sync(0xffffffffu, part, 16);
                if (lane < 2) sm[SCB + (i & 1) * 8 + kc * 4 + wgrp] = part;
            }
            if (g < 32) {               // x stream: store x[t=i+2], prefetch x[t=i+3]
                if (i <= T_N - 3) sm[XBUF + (((i + 2) & 3) * 2 + (g >> 4)) * 24 + (g & 15)] = rx;
                if (i <= T_N - 4) rx = x[xbase + (size_t)(i + 3) * 16];
            }
        }
        __syncthreads();
    }

    // ---------- attention finalize + MLP head ----------
    if (grp == 2) sm[SATT + kc * 64 + j] = aacc / as_;
    __syncthreads();

    if (tid < 256) {
        int b = tid >> 7, o = tid & 127;
        float acc = b1[o];
        const float* av = sm + SATT + b * 64;
#pragma unroll 8
        for (int k = 0; k < 64; ++k) acc += av[k] * W1[k * 128 + o];
        sm[SM1 + b * 128 + o] = fmaxf(acc, 0.f);
    }
    __syncthreads();
    if (tid < 128) {
        int b = tid >> 6, o = tid & 63;
        float acc = b2[o];
        const float* av = sm + SM1 + b * 128;
#pragma unroll 8
        for (int k = 0; k < 128; ++k) acc += av[k] * W2[k * 64 + o];
        sm[SM2 + b * 64 + o] = fmaxf(acc, 0.f);
    }
    __syncthreads();
    if (tid < 64) {
        int b = tid >> 5, o = tid & 31;
        float acc = b3[o];
        const float* av = sm + SM2 + b * 64;
#pragma unroll 8
        for (int k = 0; k < 64; ++k) acc += av[k] * W3[k * 32 + o];
        sm[SM3 + b * 32 + o] = fmaxf(acc, 0.f);
    }
    __syncthreads();
    if (tid < 4) {
        int b = tid >> 1, o = tid & 1;
        float acc = b4[o];
        const float* av = sm + SM3 + b * 32;
#pragma unroll
        for (int k = 0; k < 32; ++k) acc += av[k] * W4[k * 2 + o];
        out[((size_t)blockIdx.x * 2 + b) * 2 + o] = acc;
    }
}

extern "C" void kernel_launch(void* const* d_in, const int* in_sizes, int n_in,
                              void* d_out, int out_size) {
    (void)in_sizes; (void)n_in; (void)out_size;
    const float* x    = (const float*)d_in[0];
    const float* Wi1  = (const float*)d_in[1];
    const float* bi1  = (const float*)d_in[2];
    const float* Whr1 = (const float*)d_in[3];
    const float* Whz1 = (const float*)d_in[4];
    const float* Whn1 = (const float*)d_in[5];
    const float* bhn1 = (const float*)d_in[6];
    const float* Wi2  = (const float*)d_in[7];
    const float* bi2  = (const float*)d_in[8];
    const float* Whr2 = (const float*)d_in[9];
    const float* Whz2 = (const float*)d_in[10];
    const float* Whn2 = (const float*)d_in[11];
    const float* bhn2 = (const float*)d_in[12];
    const float* Wp   = (const float*)d_in[13];
    const float* bp   = (const float*)d_in[14];
    const float* Wa   = (const float*)d_in[15];
    const float* ba   = (const float*)d_in[16];
    const float* W1   = (const float*)d_in[17];
    const float* b1   = (const float*)d_in[18];
    const float* W2   = (const float*)d_in[19];
    const float* b2   = (const float*)d_in[20];
    const float* W3   = (const float*)d_in[21];
    const float* b3   = (const float*)d_in[22];
    const float* W4   = (const float*)d_in[23];
    const float* b4   = (const float*)d_in[24];
    float* out = (float*)d_out;

    solar_fused<<<128, 384>>>(x, Wi1, bi1, Whr1, Whz1, Whn1, bhn1,
                              Wi2, bi2, Whr2, Whz2, Whn2, bhn2,
                              Wp, bp, Wa, ba,
                              W1, b1, W2, b2, W3, b3, W4, b4, out);
}